// round 3
// baseline (speedup 1.0000x reference)
#include <cuda_runtime.h>
#include <cstdint>

// ---------------------------------------------------------------------------
// 2-layer LSTM (B=128, T=512, I=64, H=512) + linear head (C=3).
// Persistent cooperative kernel: 128 CTAs x 512 threads, one CTA per 4 hidden
// units (both layers), custom grid barrier (1 per timestep), weights in SMEM,
// cell state in registers, hidden states double-buffered in device globals.
// fp32 exact math via packed fma.rn.f32x2.
// ---------------------------------------------------------------------------

static constexpr int NB   = 128;   // batch
static constexpr int NT   = 512;   // timesteps
static constexpr int NI   = 64;    // input dim
static constexpr int NH   = 512;   // hidden dim
static constexpr int NC   = 3;     // output classes
static constexpr int NCTA = 128;   // persistent CTAs (<= 148 SMs -> co-resident)
static constexpr int NTHR = 512;   // threads per CTA = 128 batch * 4 hid
static constexpr int JPC  = NH / NCTA;   // 4 hidden units per CTA
static constexpr int W0ROW = NI + NH;    // 576 (x | h) concat for layer 0
static constexpr int W1ROW = NH + NH;    // 1024 (h1 | h2) concat for layer 1

// Hidden-state double buffers. Buffer index = t&1 (write), (t&1)^1 (read).
__device__ __align__(16) float g_hA[2][NB][NH];   // layer-0 hidden
__device__ __align__(16) float g_hB[2][NB][NH];   // layer-1 hidden
__device__ unsigned g_cnt = 0;
__device__ unsigned g_gen = 0;

// Packed fp32x2 FMA (Blackwell) — exact fp32 semantics, 2 FMAs/inst.
__device__ __forceinline__ unsigned long long ffma2(unsigned long long a,
                                                    unsigned long long b,
                                                    unsigned long long c) {
    unsigned long long d;
    asm("fma.rn.f32x2 %0, %1, %2, %3;" : "=l"(d) : "l"(a), "l"(b), "l"(c));
    return d;
}

__device__ __forceinline__ float hsum2(unsigned long long v) {
    return __uint_as_float((unsigned)(v & 0xffffffffu)) +
           __uint_as_float((unsigned)(v >> 32));
}

__device__ __forceinline__ float sigm(float v) {
    return 1.0f / (1.0f + expf(-v));
}

// Generation-counter grid barrier. `base` = g_gen snapshot at kernel entry
// (read by tid 0 before any barrier -> race-free), `idx` = barrier ordinal.
// After round idx completes, g_gen == base + idx + 1. Wrap-safe (unsigned).
__device__ __forceinline__ void grid_barrier(unsigned base, unsigned idx) {
    __syncthreads();
    if (threadIdx.x == 0) {
        __threadfence();
        if (atomicAdd(&g_cnt, 1u) == NCTA - 1) {
            g_cnt = 0;              // all arrived; no concurrent adders now
            __threadfence();
            atomicAdd(&g_gen, 1u);  // release
        } else {
            volatile unsigned* vg = &g_gen;
            while ((unsigned)(*vg - base) < idx + 1u) __nanosleep(32);
            __threadfence();
        }
    }
    __syncthreads();
}

__global__ void __launch_bounds__(NTHR, 1)
lstm_persistent(const float* __restrict__ x,
                const float* __restrict__ Wih0, const float* __restrict__ Whh0,
                const float* __restrict__ bih0, const float* __restrict__ bhh0,
                const float* __restrict__ Wih1, const float* __restrict__ Whh1,
                const float* __restrict__ bih1, const float* __restrict__ bhh1,
                const float* __restrict__ Wout, const float* __restrict__ bout,
                float* __restrict__ out) {
    extern __shared__ float smem[];
    float* sW0 = smem;                 // [16][W0ROW]  (rows: g*4 + jl)
    float* sW1 = smem + 16 * W0ROW;    // [16][W1ROW]

    const int tid = threadIdx.x;
    const int cta = blockIdx.x;
    const int j0  = cta * JPC;
    const int b   = tid >> 2;          // batch row this thread owns
    const int jl  = tid & 3;           // local hidden index
    const int j   = j0 + jl;           // global hidden index

    // ---- stage this CTA's weight slice into SMEM (concat layouts) ----
    for (int idx = tid; idx < 16 * W0ROW; idx += NTHR) {
        int r = idx / W0ROW, c = idx - r * W0ROW;
        int g = r >> 2, jj = r & 3;
        int rg = g * NH + j0 + jj;
        sW0[idx] = (c < NI) ? Wih0[rg * NI + c] : Whh0[rg * NH + (c - NI)];
    }
    for (int idx = tid; idx < 16 * W1ROW; idx += NTHR) {
        int r = idx >> 10, c = idx & 1023;
        int g = r >> 2, jj = r & 3;
        int rg = g * NH + j0 + jj;
        sW1[idx] = (c < NH) ? Wih1[rg * NH + c] : Whh1[rg * NH + (c - NH)];
    }

    // ---- zero the t=0 "previous" hidden buffers (buffer index 1) ----
    {
        int idx = cta * NTHR + tid;                // exactly covers NB*NH
        ((float*)g_hA)[NB * NH + idx] = 0.0f;
        ((float*)g_hB)[NB * NH + idx] = 0.0f;
    }

    // ---- per-thread fused biases ----
    float bi0[4], bi1[4];
    #pragma unroll
    for (int g = 0; g < 4; g++) {
        int rg = g * NH + j;
        bi0[g] = bih0[rg] + bhh0[rg];
        bi1[g] = bih1[rg] + bhh1[rg];
    }

    const ulonglong2* w0r[4];
    const ulonglong2* w1r[4];
    #pragma unroll
    for (int g = 0; g < 4; g++) {
        w0r[g] = reinterpret_cast<const ulonglong2*>(sW0 + (g * 4 + jl) * W0ROW);
        w1r[g] = reinterpret_cast<const ulonglong2*>(sW1 + (g * 4 + jl) * W1ROW);
    }

    unsigned bar_base = 0;
    if (tid == 0) bar_base = *(volatile unsigned*)&g_gen;
    unsigned bn = 0;

    grid_barrier(bar_base, bn++);   // weights + zeroed h visible everywhere

    float cA = 0.0f, cB = 0.0f;

    for (int t = 0; t < NT; t++) {
        const int p = t & 1;        // write buffer
        const int q = p ^ 1;        // read buffer

        // ================= layer 0: gates = [x_t | hA_prev] @ W0 =========
        {
            unsigned long long acc[4] = {0ull, 0ull, 0ull, 0ull};
            const ulonglong2* xv =
                reinterpret_cast<const ulonglong2*>(x + ((size_t)b * NT + t) * NI);
            #pragma unroll
            for (int k = 0; k < NI / 4; k++) {
                ulonglong2 h2 = xv[k];
                #pragma unroll
                for (int g = 0; g < 4; g++) {
                    ulonglong2 w = w0r[g][k];
                    acc[g] = ffma2(h2.x, w.x, acc[g]);
                    acc[g] = ffma2(h2.y, w.y, acc[g]);
                }
            }
            const ulonglong2* hv =
                reinterpret_cast<const ulonglong2*>(&g_hA[q][b][0]);
            #pragma unroll 4
            for (int k = 0; k < NH / 4; k++) {
                ulonglong2 h2 = hv[k];
                #pragma unroll
                for (int g = 0; g < 4; g++) {
                    ulonglong2 w = w0r[g][(NI / 4) + k];
                    acc[g] = ffma2(h2.x, w.x, acc[g]);
                    acc[g] = ffma2(h2.y, w.y, acc[g]);
                }
            }
            float pi = hsum2(acc[0]) + bi0[0];
            float pf = hsum2(acc[1]) + bi0[1];
            float pg = hsum2(acc[2]) + bi0[2];
            float po = hsum2(acc[3]) + bi0[3];
            float ig = sigm(pi), fg = sigm(pf), gg = tanhf(pg), og = sigm(po);
            cA = fg * cA + ig * gg;
            g_hA[p][b][j] = og * tanhf(cA);
        }

        grid_barrier(bar_base, bn++);   // hA[p] complete before layer 1 reads

        // ================= layer 1: gates = [hA_t | hB_prev] @ W1 ========
        {
            unsigned long long acc[4] = {0ull, 0ull, 0ull, 0ull};
            const ulonglong2* u =
                reinterpret_cast<const ulonglong2*>(&g_hA[p][b][0]);
            #pragma unroll 4
            for (int k = 0; k < NH / 4; k++) {
                ulonglong2 h2 = u[k];
                #pragma unroll
                for (int g = 0; g < 4; g++) {
                    ulonglong2 w = w1r[g][k];
                    acc[g] = ffma2(h2.x, w.x, acc[g]);
                    acc[g] = ffma2(h2.y, w.y, acc[g]);
                }
            }
            const ulonglong2* v2 =
                reinterpret_cast<const ulonglong2*>(&g_hB[q][b][0]);
            #pragma unroll 4
            for (int k = 0; k < NH / 4; k++) {
                ulonglong2 h2 = v2[k];
                #pragma unroll
                for (int g = 0; g < 4; g++) {
                    ulonglong2 w = w1r[g][(NH / 4) + k];
                    acc[g] = ffma2(h2.x, w.x, acc[g]);
                    acc[g] = ffma2(h2.y, w.y, acc[g]);
                }
            }
            float pi = hsum2(acc[0]) + bi1[0];
            float pf = hsum2(acc[1]) + bi1[1];
            float pg = hsum2(acc[2]) + bi1[2];
            float po = hsum2(acc[3]) + bi1[3];
            float ig = sigm(pi), fg = sigm(pf), gg = tanhf(pg), og = sigm(po);
            cB = fg * cB + ig * gg;
            g_hB[p][b][j] = og * tanhf(cB);
        }
        // No barrier here: next layer0 writes hA[q] which nobody still reads;
        // hB[p] readers (layer1 at t+1) sit behind the t+1 barrier.
    }

    grid_barrier(bar_base, bn++);   // final hB visible

    // ---- output head: out[b][c] = hB_last[b] . Wout[c] + bout[c] ----
    if (cta == 0 && tid < NB * NC) {
        int bb = tid / NC, cc = tid - bb * NC;
        const float* hr = &g_hB[(NT - 1) & 1][bb][0];
        const float* wr = Wout + cc * NH;
        float s0 = 0.f, s1 = 0.f, s2 = 0.f, s3 = 0.f;
        #pragma unroll 4
        for (int k = 0; k < NH; k += 4) {
            s0 += hr[k + 0] * wr[k + 0];
            s1 += hr[k + 1] * wr[k + 1];
            s2 += hr[k + 2] * wr[k + 2];
            s3 += hr[k + 3] * wr[k + 3];
        }
        out[bb * NC + cc] = s0 + s1 + s2 + s3 + bout[cc];
    }
}

extern "C" void kernel_launch(void* const* d_in, const int* in_sizes, int n_in,
                              void* d_out, int out_size) {
    (void)in_sizes; (void)n_in; (void)out_size;
    const float* x    = (const float*)d_in[0];
    const float* Wih0 = (const float*)d_in[1];
    const float* Whh0 = (const float*)d_in[2];
    const float* bih0 = (const float*)d_in[3];
    const float* bhh0 = (const float*)d_in[4];
    const float* Wih1 = (const float*)d_in[5];
    const float* Whh1 = (const float*)d_in[6];
    const float* bih1 = (const float*)d_in[7];
    const float* bhh1 = (const float*)d_in[8];
    const float* Wout = (const float*)d_in[9];
    const float* bout = (const float*)d_in[10];
    float* out = (float*)d_out;

    const size_t shbytes = (size_t)(16 * W0ROW + 16 * W1ROW) * sizeof(float); // 102400
    cudaFuncSetAttribute(lstm_persistent,
                         cudaFuncAttributeMaxDynamicSharedMemorySize,
                         (int)shbytes);
    lstm_persistent<<<NCTA, NTHR, shbytes>>>(
        x, Wih0, Whh0, bih0, bhh0, Wih1, Whh1, bih1, bhh1, Wout, bout, out);
}

// round 8
// speedup vs baseline: 4.2521x; 4.2521x over previous
#include <cuda_runtime.h>
#include <cstdint>

// ---------------------------------------------------------------------------
// 2-layer LSTM (B=128, T=512, I=64, H=512) + linear head (C=3).
// Persistent kernel: 128 CTAs x 256 threads. Each CTA owns 4 hidden units
// (both layers); each thread owns (2 batches x 4 gates). Weights in padded
// SMEM (bank-conflict-free), cell state in registers, hidden states
// double-buffered in device globals, 1 custom grid barrier per timestep.
// fp32 exact math via packed fma.rn.f32x2.
// ---------------------------------------------------------------------------

static constexpr int NB   = 128;
static constexpr int NT   = 512;
static constexpr int NI   = 64;
static constexpr int NH   = 512;
static constexpr int NC   = 3;
static constexpr int NCTA = 128;
static constexpr int NTHR = 256;           // 64 batch-groups x 4 jl
static constexpr int PW0  = 580;           // padded row stride (576+4) floats
static constexpr int PW1  = 1028;          // padded row stride (1024+4) floats

__device__ __align__(16) float g_hA[2][NB][NH];
__device__ __align__(16) float g_hB[2][NB][NH];
__device__ unsigned g_cnt = 0;
__device__ unsigned g_gen = 0;

__device__ __forceinline__ unsigned long long ffma2(unsigned long long a,
                                                    unsigned long long b,
                                                    unsigned long long c) {
    unsigned long long d;
    asm("fma.rn.f32x2 %0, %1, %2, %3;" : "=l"(d) : "l"(a), "l"(b), "l"(c));
    return d;
}

__device__ __forceinline__ float hsum2(unsigned long long v) {
    return __uint_as_float((unsigned)(v & 0xffffffffu)) +
           __uint_as_float((unsigned)(v >> 32));
}

__device__ __forceinline__ float sigm(float v) {
    return 1.0f / (1.0f + expf(-v));
}

// Generation-counter grid barrier (wrap-safe vs. entry snapshot `base`).
__device__ __forceinline__ void grid_barrier(unsigned base, unsigned idx) {
    __syncthreads();
    if (threadIdx.x == 0) {
        __threadfence();
        if (atomicAdd(&g_cnt, 1u) == NCTA - 1) {
            g_cnt = 0;
            __threadfence();
            atomicAdd(&g_gen, 1u);
        } else {
            volatile unsigned* vg = &g_gen;
            while ((unsigned)(*vg - base) < idx + 1u) __nanosleep(32);
            __threadfence();
        }
    }
    __syncthreads();
}

__global__ void __launch_bounds__(NTHR, 1)
lstm_persistent(const float* __restrict__ x,
                const float* __restrict__ Wih0, const float* __restrict__ Whh0,
                const float* __restrict__ bih0, const float* __restrict__ bhh0,
                const float* __restrict__ Wih1, const float* __restrict__ Whh1,
                const float* __restrict__ bih1, const float* __restrict__ bhh1,
                const float* __restrict__ Wout, const float* __restrict__ bout,
                float* __restrict__ out) {
    extern __shared__ float smem[];
    float* sW0 = smem;                 // [16][PW0]  rows: g*4 + jl
    float* sW1 = smem + 16 * PW0;      // [16][PW1]

    const int tid = threadIdx.x;
    const int cta = blockIdx.x;
    const int j0  = cta * 4;
    const int jl  = tid & 3;
    const int bg  = tid >> 2;          // 0..63
    const int b0  = bg * 2;
    const int b1  = b0 + 1;
    const int j   = j0 + jl;

    // ---- stage weight slices into padded SMEM ----
    for (int r = 0; r < 16; r++) {
        int g = r >> 2, jj = r & 3;
        int rg = g * NH + j0 + jj;
        for (int c = tid; c < NI + NH; c += NTHR)
            sW0[r * PW0 + c] = (c < NI) ? Wih0[rg * NI + c]
                                        : Whh0[rg * NH + (c - NI)];
        for (int c = tid; c < 2 * NH; c += NTHR)
            sW1[r * PW1 + c] = (c < NH) ? Wih1[rg * NH + c]
                                        : Whh1[rg * NH + (c - NH)];
    }

    // ---- zero t=0 "previous" buffers (buffer index 1): 2 elems/thread ----
    {
        int base = (cta * NTHR + tid) * 2;        // covers exactly NB*NH
        ((float*)g_hA)[NB * NH + base + 0] = 0.0f;
        ((float*)g_hA)[NB * NH + base + 1] = 0.0f;
        ((float*)g_hB)[NB * NH + base + 0] = 0.0f;
        ((float*)g_hB)[NB * NH + base + 1] = 0.0f;
    }

    // ---- fused biases for this thread's hidden unit j ----
    float bi0[4], bi1[4];
    #pragma unroll
    for (int g = 0; g < 4; g++) {
        int rg = g * NH + j;
        bi0[g] = bih0[rg] + bhh0[rg];
        bi1[g] = bih1[rg] + bhh1[rg];
    }

    const ulonglong2* w0r[4];
    const ulonglong2* w1r[4];
    #pragma unroll
    for (int g = 0; g < 4; g++) {
        w0r[g] = reinterpret_cast<const ulonglong2*>(sW0 + (g * 4 + jl) * PW0);
        w1r[g] = reinterpret_cast<const ulonglong2*>(sW1 + (g * 4 + jl) * PW1);
    }

    unsigned bar_base = 0;
    if (tid == 0) bar_base = *(volatile unsigned*)&g_gen;
    unsigned bn = 0;

    grid_barrier(bar_base, bn++);   // weights + zeroed buffers visible

    float cA0 = 0.f, cA1 = 0.f, cB0 = 0.f, cB1 = 0.f;

    for (int t = 0; t < NT; t++) {
        const int p = t & 1;
        const int q = p ^ 1;

        // ================= layer 0: [x_t | hA_prev] @ W0 ==================
        {
            unsigned long long acc[4][2];
            #pragma unroll
            for (int g = 0; g < 4; g++) { acc[g][0] = 0ull; acc[g][1] = 0ull; }

            const ulonglong2* xv0 =
                reinterpret_cast<const ulonglong2*>(x + ((size_t)b0 * NT + t) * NI);
            const ulonglong2* xv1 =
                reinterpret_cast<const ulonglong2*>(x + ((size_t)b1 * NT + t) * NI);
            #pragma unroll 4
            for (int k = 0; k < NI / 4; k++) {
                ulonglong2 h0 = xv0[k], h1 = xv1[k];
                #pragma unroll
                for (int g = 0; g < 4; g++) {
                    ulonglong2 w = w0r[g][k];
                    acc[g][0] = ffma2(h0.x, w.x, acc[g][0]);
                    acc[g][0] = ffma2(h0.y, w.y, acc[g][0]);
                    acc[g][1] = ffma2(h1.x, w.x, acc[g][1]);
                    acc[g][1] = ffma2(h1.y, w.y, acc[g][1]);
                }
            }
            const ulonglong2* hv0 =
                reinterpret_cast<const ulonglong2*>(&g_hA[q][b0][0]);
            const ulonglong2* hv1 =
                reinterpret_cast<const ulonglong2*>(&g_hA[q][b1][0]);
            #pragma unroll 4
            for (int k = 0; k < NH / 4; k++) {
                ulonglong2 h0 = hv0[k], h1 = hv1[k];
                #pragma unroll
                for (int g = 0; g < 4; g++) {
                    ulonglong2 w = w0r[g][(NI / 4) + k];
                    acc[g][0] = ffma2(h0.x, w.x, acc[g][0]);
                    acc[g][0] = ffma2(h0.y, w.y, acc[g][0]);
                    acc[g][1] = ffma2(h1.x, w.x, acc[g][1]);
                    acc[g][1] = ffma2(h1.y, w.y, acc[g][1]);
                }
            }
            {
                float pi = hsum2(acc[0][0]) + bi0[0];
                float pf = hsum2(acc[1][0]) + bi0[1];
                float pg = hsum2(acc[2][0]) + bi0[2];
                float po = hsum2(acc[3][0]) + bi0[3];
                float ig = sigm(pi), fg = sigm(pf), gg = tanhf(pg), og = sigm(po);
                cA0 = fg * cA0 + ig * gg;
                g_hA[p][b0][j] = og * tanhf(cA0);
            }
            {
                float pi = hsum2(acc[0][1]) + bi0[0];
                float pf = hsum2(acc[1][1]) + bi0[1];
                float pg = hsum2(acc[2][1]) + bi0[2];
                float po = hsum2(acc[3][1]) + bi0[3];
                float ig = sigm(pi), fg = sigm(pf), gg = tanhf(pg), og = sigm(po);
                cA1 = fg * cA1 + ig * gg;
                g_hA[p][b1][j] = og * tanhf(cA1);
            }
        }

        grid_barrier(bar_base, bn++);   // hA[p] complete before layer 1 reads

        // ================= layer 1: [hA_t | hB_prev] @ W1 =================
        {
            unsigned long long acc[4][2];
            #pragma unroll
            for (int g = 0; g < 4; g++) { acc[g][0] = 0ull; acc[g][1] = 0ull; }

            const ulonglong2* u0 =
                reinterpret_cast<const ulonglong2*>(&g_hA[p][b0][0]);
            const ulonglong2* u1 =
                reinterpret_cast<const ulonglong2*>(&g_hA[p][b1][0]);
            #pragma unroll 4
            for (int k = 0; k < NH / 4; k++) {
                ulonglong2 h0 = u0[k], h1 = u1[k];
                #pragma unroll
                for (int g = 0; g < 4; g++) {
                    ulonglong2 w = w1r[g][k];
                    acc[g][0] = ffma2(h0.x, w.x, acc[g][0]);
                    acc[g][0] = ffma2(h0.y, w.y, acc[g][0]);
                    acc[g][1] = ffma2(h1.x, w.x, acc[g][1]);
                    acc[g][1] = ffma2(h1.y, w.y, acc[g][1]);
                }
            }
            const ulonglong2* v0 =
                reinterpret_cast<const ulonglong2*>(&g_hB[q][b0][0]);
            const ulonglong2* v1 =
                reinterpret_cast<const ulonglong2*>(&g_hB[q][b1][0]);
            #pragma unroll 4
            for (int k = 0; k < NH / 4; k++) {
                ulonglong2 h0 = v0[k], h1 = v1[k];
                #pragma unroll
                for (int g = 0; g < 4; g++) {
                    ulonglong2 w = w1r[g][(NH / 4) + k];
                    acc[g][0] = ffma2(h0.x, w.x, acc[g][0]);
                    acc[g][0] = ffma2(h0.y, w.y, acc[g][0]);
                    acc[g][1] = ffma2(h1.x, w.x, acc[g][1]);
                    acc[g][1] = ffma2(h1.y, w.y, acc[g][1]);
                }
            }
            {
                float pi = hsum2(acc[0][0]) + bi1[0];
                float pf = hsum2(acc[1][0]) + bi1[1];
                float pg = hsum2(acc[2][0]) + bi1[2];
                float po = hsum2(acc[3][0]) + bi1[3];
                float ig = sigm(pi), fg = sigm(pf), gg = tanhf(pg), og = sigm(po);
                cB0 = fg * cB0 + ig * gg;
                g_hB[p][b0][j] = og * tanhf(cB0);
            }
            {
                float pi = hsum2(acc[0][1]) + bi1[0];
                float pf = hsum2(acc[1][1]) + bi1[1];
                float pg = hsum2(acc[2][1]) + bi1[2];
                float po = hsum2(acc[3][1]) + bi1[3];
                float ig = sigm(pi), fg = sigm(pf), gg = tanhf(pg), og = sigm(po);
                cB1 = fg * cB1 + ig * gg;
                g_hB[p][b1][j] = og * tanhf(cB1);
            }
        }
        // No barrier here (verified safe): layer1(t) writes hB[p] whose only
        // readers (layer1 at t+1) sit behind the t+1 mid-barrier; layer0(t+1)
        // touches only hA buffers no one still reads.
    }

    grid_barrier(bar_base, bn++);

    // ---- output head ----
    if (cta == 0) {
        for (int idx = tid; idx < NB * NC; idx += NTHR) {
            int bb = idx / NC, cc = idx - bb * NC;
            const float* hr = &g_hB[(NT - 1) & 1][bb][0];
            const float* wr = Wout + cc * NH;
            float s0 = 0.f, s1 = 0.f, s2 = 0.f, s3 = 0.f;
            #pragma unroll 4
            for (int k = 0; k < NH; k += 4) {
                s0 += hr[k + 0] * wr[k + 0];
                s1 += hr[k + 1] * wr[k + 1];
                s2 += hr[k + 2] * wr[k + 2];
                s3 += hr[k + 3] * wr[k + 3];
            }
            out[bb * NC + cc] = s0 + s1 + s2 + s3 + bout[cc];
        }
    }
}

extern "C" void kernel_launch(void* const* d_in, const int* in_sizes, int n_in,
                              void* d_out, int out_size) {
    (void)in_sizes; (void)n_in; (void)out_size;
    const float* x    = (const float*)d_in[0];
    const float* Wih0 = (const float*)d_in[1];
    const float* Whh0 = (const float*)d_in[2];
    const float* bih0 = (const float*)d_in[3];
    const float* bhh0 = (const float*)d_in[4];
    const float* Wih1 = (const float*)d_in[5];
    const float* Whh1 = (const float*)d_in[6];
    const float* bih1 = (const float*)d_in[7];
    const float* bhh1 = (const float*)d_in[8];
    const float* Wout = (const float*)d_in[9];
    const float* bout = (const float*)d_in[10];
    float* out = (float*)d_out;

    const size_t shbytes = (size_t)(16 * PW0 + 16 * PW1) * sizeof(float); // 102912
    cudaFuncSetAttribute(lstm_persistent,
                         cudaFuncAttributeMaxDynamicSharedMemorySize,
                         (int)shbytes);
    lstm_persistent<<<NCTA, NTHR, shbytes>>>(
        x, Wih0, Whh0, bih0, bhh0, Wih1, Whh1, bih1, bhh1, Wout, bout, out);
}